// round 16
// baseline (speedup 1.0000x reference)
#include <cuda_runtime.h>
#include <cuda_fp16.h>
#include <cstdint>
#include <math.h>

constexpr int BB  = 256;
constexpr int THN = 32;
constexpr int TFN = 16;
constexpr int SS  = 512;
constexpr int AS  = 128;
constexpr int FS  = 1024;
constexpr int G3  = 3072;
constexpr int TT  = 65;

// ---------------- scratch (device globals; no allocation allowed) ----------
__device__ float g_gi  [TT * BB * G3];
__device__ float g_gia [TFN * BB * G3];
__device__ float g_gh0 [BB * G3];
__device__ float g_gh1 [BB * G3];
__device__ float g_gi1 [BB * G3];
__device__ float g_h0f [BB * FS];
__device__ float g_h1f [BB * FS];
__device__ unsigned int g_bar;                  // scan-kernel grid barrier
__device__ float g_slab[6 * BB * G3];           // split-K partial slabs
__device__ unsigned int g_cnt[2 * 64];          // split-K tile counters (zero-init)

// fp16 activation planes
__device__ __half g_xs_h[TT * BB * FS];
__device__ __half g_xa  [TFN * BB * FS];
__device__ __half g_h0h[BB * FS];
__device__ __half g_h1h[BB * FS];
__device__ __half g_xh [BB * FS];
__device__ __half g_sh [BB * SS];
__device__ __half g_hs [BB * THN * SS];
__device__ __half g_ha [BB * THN * AS];
__device__ __half g_ps [BB * SS];
__device__ __half g_fa [BB * TFN * AS];

// split fp16 weights (hi/lo), laid out [N, K]
__device__ __half g_Ws_hi [FS * SS],     g_Ws_lo [FS * SS];
__device__ __half g_Wa_hi [FS * AS],     g_Wa_lo [FS * AS];
__device__ __half g_Wih_hi[2 * G3 * FS], g_Wih_lo[2 * G3 * FS];
__device__ __half g_Whh_hi[2 * G3 * FS], g_Whh_lo[2 * G3 * FS];
__device__ __half g_Ws2_hi[SS * FS],     g_Ws2_lo[SS * FS];

// ---------------- PTX helpers ----------------------------------------------
__device__ __forceinline__ uint32_t smem_u32(const void* p) {
    uint32_t a;
    asm("{ .reg .u64 t; cvta.to.shared.u64 t, %1; cvt.u32.u64 %0, t; }"
        : "=r"(a) : "l"(p));
    return a;
}

__device__ __forceinline__ void ldmx4(uint32_t* r, uint32_t addr) {
    asm volatile("ldmatrix.sync.aligned.m8n8.x4.shared.b16 {%0,%1,%2,%3}, [%4];"
                 : "=r"(r[0]), "=r"(r[1]), "=r"(r[2]), "=r"(r[3]) : "r"(addr));
}

__device__ __forceinline__ void mma16816(float* d, const uint32_t* a, const uint32_t* b) {
    asm volatile(
        "mma.sync.aligned.m16n8k16.row.col.f32.f16.f16.f32 "
        "{%0,%1,%2,%3}, {%4,%5,%6,%7}, {%8,%9}, {%0,%1,%2,%3};"
        : "+f"(d[0]), "+f"(d[1]), "+f"(d[2]), "+f"(d[3])
        : "r"(a[0]), "r"(a[1]), "r"(a[2]), "r"(a[3]), "r"(b[0]), "r"(b[1]));
}

__device__ __forceinline__ void cpasync16(uint32_t dst, const void* src) {
    asm volatile("cp.async.cg.shared.global [%0], [%1], 16;" :: "r"(dst), "l"(src));
}
#define CP_COMMIT()  asm volatile("cp.async.commit_group;")
#define CP_WAIT1()   asm volatile("cp.async.wait_group 1;")
#define CP_WAIT0()   asm volatile("cp.async.wait_group 0;")

constexpr int ST_A  = 0;
constexpr int ST_WH = 16384;
constexpr int ST_WL = 32768;
constexpr int STAGE = 49152;
constexpr int SMEM_BYTES = 98304;

__device__ __forceinline__ float act_f(float v, int act) {
    if (act == 1) return tanhf(v);
    if (act == 2) return 1.0f / (1.0f + expf(-v));
    return v;
}

// ---------------- shared GEMM tile core (chunk range [c0, c1)) --------------
__device__ __forceinline__ void issue_stage_p(
    const __half* A, int64_t lda, const __half* Wh, const __half* Wl,
    int K, int row0, int col0, int k0, uint32_t sbase, int tid)
{
    const int row  = tid >> 1;
    const int colb = (tid & 1) * 64;
    const int cole = colb >> 1;
    const uint32_t dbase  = (uint32_t)(row * 128);
    const uint32_t swmask = (uint32_t)((row & 7) << 4);
    const __half* a_p = A  + (size_t)(row0 + row) * lda + k0 + cole;
    const __half* w_h = Wh + (size_t)(col0 + row) * K + k0 + cole;
    const __half* w_l = Wl + (size_t)(col0 + row) * K + k0 + cole;
    #pragma unroll
    for (int j = 0; j < 4; j++) {
        uint32_t sw = (dbase + (uint32_t)(colb + j * 16)) ^ swmask;
        cpasync16(sbase + ST_A  + sw, a_p + j * 8);
        cpasync16(sbase + ST_WH + sw, w_h + j * 8);
        cpasync16(sbase + ST_WL + sw, w_l + j * 8);
    }
}

__device__ __forceinline__ void gemm128_acc(
    const __half* A, int64_t lda, const __half* Wh, const __half* Wl,
    int K, int row0, int col0, uint32_t sb, int tid, int m0w, int n0w, int lane,
    float acc[4][4][4], int c0, int c1)
{
    issue_stage_p(A, lda, Wh, Wl, K, row0, col0, c0 << 6, sb, tid);
    CP_COMMIT();
    if (c1 - c0 > 1) {
        issue_stage_p(A, lda, Wh, Wl, K, row0, col0, (c0 + 1) << 6, sb + STAGE, tid);
        CP_COMMIT();
    }

    #pragma unroll
    for (int i = 0; i < 4; i++)
        #pragma unroll
        for (int j = 0; j < 4; j++)
            #pragma unroll
            for (int q = 0; q < 4; q++) acc[i][j][q] = 0.0f;

    const uint32_t a_lrow  = (uint32_t)(lane & 15);
    const uint32_t a_lcolb = (uint32_t)((lane >> 4) * 16);
    const uint32_t b_lrow  = (uint32_t)((lane & 7) + ((lane >> 4) & 1) * 8);
    const uint32_t b_lcolb = (uint32_t)(((lane >> 3) & 1) * 16);

    for (int c = c0; c < c1; c++) {
        if (c + 1 < c1) { CP_WAIT1(); } else { CP_WAIT0(); }
        __syncthreads();
        const uint32_t st = sb + (uint32_t)(((c - c0) & 1) * STAGE);

        #pragma unroll
        for (int ks = 0; ks < 4; ks++) {
            const uint32_t kc = (uint32_t)(ks * 32);
            uint32_t Af[16], Bh[8], Bl[8];
            #pragma unroll
            for (int mt = 0; mt < 4; mt++) {
                uint32_t r = (uint32_t)(m0w + mt * 16) + a_lrow;
                uint32_t off = r * 128 + ((kc + a_lcolb) ^ ((r & 7) << 4));
                ldmx4(Af + mt * 4, st + ST_A + off);
            }
            #pragma unroll
            for (int p = 0; p < 2; p++) {
                uint32_t r = (uint32_t)(n0w + p * 16) + b_lrow;
                uint32_t off = r * 128 + ((kc + b_lcolb) ^ ((r & 7) << 4));
                ldmx4(Bh + p * 4, st + ST_WH + off);
                ldmx4(Bl + p * 4, st + ST_WL + off);
            }
            #pragma unroll
            for (int mt = 0; mt < 4; mt++) {
                #pragma unroll
                for (int nt = 0; nt < 4; nt++) {
                    const uint32_t* bh = &Bh[(nt >> 1) * 4 + (nt & 1) * 2];
                    const uint32_t* bl = &Bl[(nt >> 1) * 4 + (nt & 1) * 2];
                    mma16816(acc[mt][nt], Af + mt * 4, bh);
                    mma16816(acc[mt][nt], Af + mt * 4, bl);
                }
            }
        }
        __syncthreads();
        if (c + 2 < c1) {
            issue_stage_p(A, lda, Wh, Wl, K, row0, col0, (c + 2) << 6,
                          sb + (uint32_t)(((c - c0) & 1) * STAGE), tid);
            CP_COMMIT();
        }
    }
}

// ---------------- general GEMM kernel (with optional split-K) ---------------
struct GTask {
    const __half* A; int64_t lda;
    const __half *Wh, *Wl;
    const float* bias;
    float* Cf; int64_t ldcf;
    __half* Ch; int64_t ldch;
    int act; int rowmap;
};

__global__ void __launch_bounds__(256, 1) mm_kernel(
    GTask T0, GTask T1, GTask T2, int K, int splitk)
{
    extern __shared__ __align__(16) char sm[];
    const int task = blockIdx.z / splitk;
    const int ksl  = blockIdx.z % splitk;
    const GTask T = (task == 0) ? T0 : (task == 1 ? T1 : T2);
    const uint32_t sb = smem_u32(sm);
    const int tid  = threadIdx.x;
    const int wid  = tid >> 5, lane = tid & 31;
    const int row0 = blockIdx.y * 128, col0 = blockIdx.x * 128;
    const int m0w  = (wid >> 2) * 64;
    const int n0w  = (wid & 3) * 32;
    const int NC = K >> 6;
    const int c0 = (NC * ksl) / splitk, c1 = (NC * (ksl + 1)) / splitk;

    float acc[4][4][4];
    gemm128_acc(T.A, T.lda, T.Wh, T.Wl, K, row0, col0, sb, tid, m0w, n0w, lane, acc, c0, c1);

    const int tq = lane >> 2, tr = lane & 3;
    const int Ntot = gridDim.x * 128;

    if (splitk > 1) {
        float* reg = g_slab + (size_t)(task * splitk + ksl) * (BB * G3);
        #pragma unroll
        for (int mt = 0; mt < 4; mt++)
            #pragma unroll
            for (int half = 0; half < 2; half++) {
                int m = row0 + m0w + mt * 16 + half * 8 + tq;
                #pragma unroll
                for (int nt = 0; nt < 4; nt++) {
                    int n = col0 + n0w + nt * 8 + tr * 2;
                    float2 o;
                    o.x = acc[mt][nt][half * 2 + 0];
                    o.y = acc[mt][nt][half * 2 + 1];
                    *(float2*)(reg + (size_t)m * Ntot + n) = o;
                }
            }
        __threadfence();
        __syncthreads();
        __shared__ int lastflag;
        const int tile = blockIdx.y * gridDim.x + blockIdx.x;
        if (tid == 0)
            lastflag = (atomicAdd(&g_cnt[task * 64 + tile], 1u) == (unsigned)(splitk - 1));
        __syncthreads();
        if (!lastflag) return;
        __threadfence();
        #pragma unroll
        for (int mt = 0; mt < 4; mt++)
            #pragma unroll
            for (int half = 0; half < 2; half++) {
                int m = row0 + m0w + mt * 16 + half * 8 + tq;
                #pragma unroll
                for (int nt = 0; nt < 4; nt++) {
                    int n = col0 + n0w + nt * 8 + tr * 2;
                    for (int k2 = 0; k2 < splitk; k2++) {
                        if (k2 == ksl) continue;
                        const float* r2 = g_slab + (size_t)(task * splitk + k2) * (BB * G3);
                        float2 v = __ldcg((const float2*)(r2 + (size_t)m * Ntot + n));
                        acc[mt][nt][half * 2 + 0] += v.x;
                        acc[mt][nt][half * 2 + 1] += v.y;
                    }
                }
            }
        if (tid == 0) g_cnt[task * 64 + tile] = 0u;
    }

    #pragma unroll
    for (int mt = 0; mt < 4; mt++) {
        #pragma unroll
        for (int half = 0; half < 2; half++) {
            int m = row0 + m0w + mt * 16 + half * 8 + tq;
            int mp;
            if (T.rowmap == 1)      mp = ((m & 31) << 1) * BB + (m >> 5);
            else if (T.rowmap == 2) mp = (((m & 31) << 1) + 1) * BB + (m >> 5);
            else if (T.rowmap == 3) mp = (m & 15) * BB + (m >> 4);
            else                    mp = m;
            float* cf = T.Cf ? T.Cf + (size_t)mp * T.ldcf : nullptr;
            __half* ch = T.Ch ? T.Ch + (size_t)mp * T.ldch : nullptr;
            #pragma unroll
            for (int nt = 0; nt < 4; nt++) {
                int n = col0 + n0w + nt * 8 + tr * 2;
                float2 bv = *(const float2*)(T.bias + n);
                float vx = act_f(acc[mt][nt][half * 2 + 0] + bv.x, T.act);
                float vy = act_f(acc[mt][nt][half * 2 + 1] + bv.y, T.act);
                if (cf) { float2 o; o.x = vx; o.y = vy; *(float2*)(cf + n) = o; }
                if (ch) {
                    uint32_t hp = (uint32_t)__half_as_ushort(__float2half_rn(vx))
                                | ((uint32_t)__half_as_ushort(__float2half_rn(vy)) << 16);
                    *(uint32_t*)(ch + n) = hp;
                }
            }
        }
    }
}

// ---------------- persistent scan kernel ------------------------------------
__device__ __forceinline__ void grid_bar(unsigned target) {
    __syncthreads();
    if (threadIdx.x == 0) {
        __threadfence();
        atomicAdd(&g_bar, 1u);
        unsigned v;
        do {
            asm volatile("ld.global.cg.u32 %0, [%1];" : "=r"(v) : "l"(&g_bar));
            if (v < target) __nanosleep(64);
        } while (v < target);
    }
    __syncthreads();
}

__global__ void __launch_bounds__(256, 1) scan_kernel(
    float* h0f, float* h1f, __half* h0h, __half* h1h,
    const __half* Whh0h, const __half* Whh0l,
    const __half* Wih1h, const __half* Wih1l,
    const __half* Whh1h, const __half* Whh1l,
    const float* bhh0, const float* bih1, const float* bhh1,
    const float* gi, float* gh0b, float* gi1b, float* gh1b)
{
    extern __shared__ __align__(16) char sm[];
    const uint32_t sb = smem_u32(sm);
    const int tid  = threadIdx.x;
    const int wid  = tid >> 5, lane = tid & 31;
    const int m0w  = (wid >> 2) * 64;
    const int n0w  = (wid & 3) * 32;

    const int cta = blockIdx.x;
    const int mat = cta % 3;
    const int tilid = cta / 3;
    const int col0 = (tilid % 24) * 128;
    const int row0 = (tilid / 24) * 128;

    const __half* Asrc; const __half *Wh, *Wl; const float* bias; float* Cout;
    if (mat == 0)      { Asrc = h0h; Wh = Whh0h; Wl = Whh0l; bias = bhh0; Cout = gh0b; }
    else if (mat == 1) { Asrc = h0h; Wh = Wih1h; Wl = Wih1l; bias = bih1; Cout = gi1b; }
    else               { Asrc = h1h; Wh = Whh1h; Wl = Whh1l; bias = bhh1; Cout = gh1b; }

    const int gtid = cta * 256 + tid;
    constexpr int NT = 144 * 256;
    constexpr int NP = BB * FS / 2;
    const int tq = lane >> 2, tr = lane & 3;

    unsigned epoch = 0;

    for (int it = 0; it < TT + 1; it++) {
        const bool do_gemm = (mat == 0) ? (it <= TT - 1) : (it >= 1);
        if (do_gemm) {
            float acc[4][4][4];
            gemm128_acc(Asrc, FS, Wh, Wl, FS, row0, col0, sb, tid, m0w, n0w, lane,
                        acc, 0, FS >> 6);
            #pragma unroll
            for (int mt = 0; mt < 4; mt++) {
                #pragma unroll
                for (int half = 0; half < 2; half++) {
                    int m = row0 + m0w + mt * 16 + half * 8 + tq;
                    float* cf = Cout + (size_t)m * G3;
                    #pragma unroll
                    for (int nt = 0; nt < 4; nt++) {
                        int n = col0 + n0w + nt * 8 + tr * 2;
                        float2 bv = *(const float2*)(bias + n);
                        float2 o;
                        o.x = acc[mt][nt][half * 2 + 0] + bv.x;
                        o.y = acc[mt][nt][half * 2 + 1] + bv.y;
                        *(float2*)(cf + n) = o;
                    }
                }
            }
        }
        grid_bar(++epoch * 144u);

        if (it <= TT - 1) {
            const float* gi0 = gi + (size_t)it * BB * G3;
            for (int p = gtid; p < NP; p += NT) {
                int m = p >> 9, j = (p & 511) << 1;
                size_t base = (size_t)m * G3 + j;
                float2 ir = *(const float2*)(gi0 + base);
                float2 iz = *(const float2*)(gi0 + base + FS);
                float2 in = *(const float2*)(gi0 + base + 2 * FS);
                float2 hr = __ldcg((const float2*)(gh0b + base));
                float2 hz = __ldcg((const float2*)(gh0b + base + FS));
                float2 hn = __ldcg((const float2*)(gh0b + base + 2 * FS));
                int hidx = m * FS + j;
                float2 hold = *(const float2*)(h0f + hidx);
                float r0 = 1.0f / (1.0f + expf(-(ir.x + hr.x)));
                float z0 = 1.0f / (1.0f + expf(-(iz.x + hz.x)));
                float n0 = tanhf(in.x + r0 * hn.x);
                float v0 = (1.0f - z0) * n0 + z0 * hold.x;
                float r1 = 1.0f / (1.0f + expf(-(ir.y + hr.y)));
                float z1 = 1.0f / (1.0f + expf(-(iz.y + hz.y)));
                float n1 = tanhf(in.y + r1 * hn.y);
                float v1 = (1.0f - z1) * n1 + z1 * hold.y;
                float2 o; o.x = v0; o.y = v1;
                *(float2*)(h0f + hidx) = o;
                uint32_t hp = (uint32_t)__half_as_ushort(__float2half_rn(v0))
                            | ((uint32_t)__half_as_ushort(__float2half_rn(v1)) << 16);
                *(uint32_t*)(h0h + hidx) = hp;
            }
        }
        if (it >= 1) {
            for (int p = gtid; p < NP; p += NT) {
                int m = p >> 9, j = (p & 511) << 1;
                size_t base = (size_t)m * G3 + j;
                float2 ir = __ldcg((const float2*)(gi1b + base));
                float2 iz = __ldcg((const float2*)(gi1b + base + FS));
                float2 in = __ldcg((const float2*)(gi1b + base + 2 * FS));
                float2 hr = __ldcg((const float2*)(gh1b + base));
                float2 hz = __ldcg((const float2*)(gh1b + base + FS));
                float2 hn = __ldcg((const float2*)(gh1b + base + 2 * FS));
                int hidx = m * FS + j;
                float2 hold = *(const float2*)(h1f + hidx);
                float r0 = 1.0f / (1.0f + expf(-(ir.x + hr.x)));
                float z0 = 1.0f / (1.0f + expf(-(iz.x + hz.x)));
                float n0 = tanhf(in.x + r0 * hn.x);
                float v0 = (1.0f - z0) * n0 + z0 * hold.x;
                float r1 = 1.0f / (1.0f + expf(-(ir.y + hr.y)));
                float z1 = 1.0f / (1.0f + expf(-(iz.y + hz.y)));
                float n1 = tanhf(in.y + r1 * hn.y);
                float v1 = (1.0f - z1) * n1 + z1 * hold.y;
                float2 o; o.x = v0; o.y = v1;
                *(float2*)(h1f + hidx) = o;
                uint32_t hp = (uint32_t)__half_as_ushort(__float2half_rn(v0))
                            | ((uint32_t)__half_as_ushort(__float2half_rn(v1)) << 16);
                *(uint32_t*)(h1h + hidx) = hp;
            }
        }
        grid_bar(++epoch * 144u);
    }
}

// ---------------- elementwise kernels --------------------------------------
__global__ void split_w_kernel(const float* __restrict__ w,
                               __half* __restrict__ hi,
                               __half* __restrict__ lo, int n)
{
    int i = blockIdx.x * blockDim.x + threadIdx.x;
    if (i < n) {
        float v = w[i];
        __half h = __float2half_rn(v);
        hi[i] = h;
        lo[i] = __float2half_rn(v - __half2float(h));
    }
}

__global__ void tohalf_kernel(const float* __restrict__ w,
                              __half* __restrict__ o, int n)
{
    int i = blockIdx.x * blockDim.x + threadIdx.x;
    if (i < n) o[i] = __float2half_rn(w[i]);
}

__global__ void gru_combine1(
    const float* __restrict__ gi0, const float* __restrict__ gh0,
    float* __restrict__ hf, __half* __restrict__ hh)
{
    int p = blockIdx.x * blockDim.x + threadIdx.x;
    int m = p >> 9;
    int j = (p & 511) * 2;
    size_t base = (size_t)m * G3 + j;
    float2 ir = *(const float2*)(gi0 + base);
    float2 iz = *(const float2*)(gi0 + base + FS);
    float2 in = *(const float2*)(gi0 + base + 2 * FS);
    float2 hr = *(const float2*)(gh0 + base);
    float2 hz = *(const float2*)(gh0 + base + FS);
    float2 hn = *(const float2*)(gh0 + base + 2 * FS);
    int hidx = m * FS + j;
    float2 hold = *(const float2*)(hf + hidx);

    float r0 = 1.0f / (1.0f + expf(-(ir.x + hr.x)));
    float z0 = 1.0f / (1.0f + expf(-(iz.x + hz.x)));
    float n0 = tanhf(in.x + r0 * hn.x);
    float v0 = (1.0f - z0) * n0 + z0 * hold.x;
    float r1 = 1.0f / (1.0f + expf(-(ir.y + hr.y)));
    float z1 = 1.0f / (1.0f + expf(-(iz.y + hz.y)));
    float n1 = tanhf(in.y + r1 * hn.y);
    float v1 = (1.0f - z1) * n1 + z1 * hold.y;

    float2 o; o.x = v0; o.y = v1;
    *(float2*)(hf + hidx) = o;
    uint32_t hp = (uint32_t)__half_as_ushort(__float2half_rn(v0))
                | ((uint32_t)__half_as_ushort(__float2half_rn(v1)) << 16);
    *(uint32_t*)(hh + hidx) = hp;
}

__global__ void reward_kernel(const float* __restrict__ h1,
                              const float* __restrict__ Wr,
                              const float* __restrict__ br,
                              float* __restrict__ out_r, int t)
{
    int g = blockIdx.x * blockDim.x + threadIdx.x;
    int warp = g >> 5, lane = g & 31;
    if (warp >= BB) return;
    const float* hr = h1 + (size_t)warp * FS;
    float s = 0.0f;
    #pragma unroll 8
    for (int k = lane; k < FS; k += 32) s += hr[k] * Wr[k];
    #pragma unroll
    for (int o = 16; o; o >>= 1) s += __shfl_xor_sync(0xFFFFFFFFu, s, o);
    if (lane == 0)
        out_r[warp * TFN + t] = 1.0f / (1.0f + expf(-(s + br[0])));
}

__global__ void zero_h(float* __restrict__ a, float* __restrict__ b,
                       __half* __restrict__ ah, __half* __restrict__ bh)
{
    int idx = blockIdx.x * blockDim.x + threadIdx.x;
    if (idx == 0) g_bar = 0u;
    if (idx < 128) g_cnt[idx] = 0u;
    if (idx < BB * FS) {
        a[idx] = 0.0f; b[idx] = 0.0f;
        ah[idx] = __float2half(0.0f); bh[idx] = __float2half(0.0f);
    }
}

// ---------------- host orchestration ---------------------------------------
static GTask mk(const __half* A, int64_t lda,
                const __half* Wh, const __half* Wl, const float* bias,
                float* Cf, int64_t ldcf, __half* Ch, int64_t ldch,
                int act, int rowmap)
{
    GTask t; t.A = A; t.lda = lda; t.Wh = Wh; t.Wl = Wl; t.bias = bias;
    t.Cf = Cf; t.ldcf = ldcf; t.Ch = Ch; t.ldch = ldch;
    t.act = act; t.rowmap = rowmap;
    return t;
}

static void mm1(const GTask& a, int M, int N, int K, int splitk = 1) {
    dim3 g(N / 128, M / 128, splitk);
    mm_kernel<<<g, 256, SMEM_BYTES>>>(a, a, a, K, splitk);
}
static void mm2(const GTask& a, const GTask& b, int M, int N, int K, int splitk = 1) {
    dim3 g(N / 128, M / 128, 2 * splitk);
    mm_kernel<<<g, 256, SMEM_BYTES>>>(a, b, a, K, splitk);
}

extern "C" void kernel_launch(void* const* d_in, const int* in_sizes, int n_in,
                              void* d_out, int out_size)
{
    const float* history_s = (const float*)d_in[0];
    const float* history_a = (const float*)d_in[1];
    const float* present_s = (const float*)d_in[2];
    const float* future_a  = (const float*)d_in[3];
    const float* Ws  = (const float*)d_in[4];
    const float* bs  = (const float*)d_in[5];
    const float* Wa  = (const float*)d_in[6];
    const float* ba  = (const float*)d_in[7];
    const float* Wih = (const float*)d_in[8];
    const float* Whh = (const float*)d_in[9];
    const float* bih = (const float*)d_in[10];
    const float* bhh = (const float*)d_in[11];
    const float* Wr  = (const float*)d_in[12];
    const float* br  = (const float*)d_in[13];
    const float* Ws2 = (const float*)d_in[14];
    const float* bs2 = (const float*)d_in[15];

    float* out_r = (float*)d_out;
    float* out_s = (float*)d_out + BB * TFN;

    cudaFuncSetAttribute(mm_kernel,   cudaFuncAttributeMaxDynamicSharedMemorySize, SMEM_BYTES);
    cudaFuncSetAttribute(scan_kernel, cudaFuncAttributeMaxDynamicSharedMemorySize, SMEM_BYTES);

    float *gi, *gia, *gh0b, *gh1b, *gi1b, *h0f, *h1f;
    cudaGetSymbolAddress((void**)&gi,   g_gi);
    cudaGetSymbolAddress((void**)&gia,  g_gia);
    cudaGetSymbolAddress((void**)&gh0b, g_gh0);
    cudaGetSymbolAddress((void**)&gh1b, g_gh1);
    cudaGetSymbolAddress((void**)&gi1b, g_gi1);
    cudaGetSymbolAddress((void**)&h0f,  g_h0f);
    cudaGetSymbolAddress((void**)&h1f,  g_h1f);

    __half *xs_h, *xa, *h0h, *h1h, *xh, *sh, *hs, *ha, *ps, *fa;
    cudaGetSymbolAddress((void**)&xs_h, g_xs_h);
    cudaGetSymbolAddress((void**)&xa,  g_xa);
    cudaGetSymbolAddress((void**)&h0h, g_h0h);
    cudaGetSymbolAddress((void**)&h1h, g_h1h);
    cudaGetSymbolAddress((void**)&xh,  g_xh);
    cudaGetSymbolAddress((void**)&sh,  g_sh);
    cudaGetSymbolAddress((void**)&hs,  g_hs);
    cudaGetSymbolAddress((void**)&ha,  g_ha);
    cudaGetSymbolAddress((void**)&ps,  g_ps);
    cudaGetSymbolAddress((void**)&fa,  g_fa);

    __half *Ws_h, *Ws_l, *Wa_h, *Wa_l, *Wih_h, *Wih_l, *Whh_h, *Whh_l, *Ws2_h, *Ws2_l;
    cudaGetSymbolAddress((void**)&Ws_h,  g_Ws_hi);  cudaGetSymbolAddress((void**)&Ws_l,  g_Ws_lo);
    cudaGetSymbolAddress((void**)&Wa_h,  g_Wa_hi);  cudaGetSymbolAddress((void**)&Wa_l,  g_Wa_lo);
    cudaGetSymbolAddress((void**)&Wih_h, g_Wih_hi); cudaGetSymbolAddress((void**)&Wih_l, g_Wih_lo);
    cudaGetSymbolAddress((void**)&Whh_h, g_Whh_hi); cudaGetSymbolAddress((void**)&Whh_l, g_Whh_lo);
    cudaGetSymbolAddress((void**)&Ws2_h, g_Ws2_hi); cudaGetSymbolAddress((void**)&Ws2_l, g_Ws2_lo);

    auto splitw = [](const float* w, __half* hi, __half* lo, int n) {
        split_w_kernel<<<(n + 255) / 256, 256>>>(w, hi, lo, n);
    };
    auto tohalf = [](const float* w, __half* o, int n) {
        tohalf_kernel<<<(n + 255) / 256, 256>>>(w, o, n);
    };
    splitw(Ws,  Ws_h,  Ws_l,  FS * SS);
    splitw(Wa,  Wa_h,  Wa_l,  FS * AS);
    splitw(Wih, Wih_h, Wih_l, 2 * G3 * FS);
    splitw(Whh, Whh_h, Whh_l, 2 * G3 * FS);
    splitw(Ws2, Ws2_h, Ws2_l, SS * FS);
    tohalf(history_s, hs, BB * THN * SS);
    tohalf(history_a, ha, BB * THN * AS);
    tohalf(present_s, ps, BB * SS);
    tohalf(future_a,  fa, BB * TFN * AS);

    const __half *Wih0h = Wih_h, *Wih0l = Wih_l;
    const __half *Wih1h = Wih_h + (size_t)G3 * FS, *Wih1l = Wih_l + (size_t)G3 * FS;
    const __half *Whh0h = Whh_h, *Whh0l = Whh_l;
    const __half *Whh1h = Whh_h + (size_t)G3 * FS, *Whh1l = Whh_l + (size_t)G3 * FS;
    const float *bih0 = bih, *bih1 = bih + G3, *bhh0 = bhh, *bhh1 = bhh + G3;

    zero_h<<<(BB * FS + 255) / 256, 256>>>(h0f, h1f, h0h, h1h);

    // prefix embeddings -> xs plane [t][b][f] (interleaved; present last)
    mm1(mk(hs, SS, Ws_h, Ws_l, bs, nullptr, 0, xs_h, FS, 1, 1), BB * THN, FS, SS);
    mm1(mk(ha, AS, Wa_h, Wa_l, ba, nullptr, 0, xs_h, FS, 1, 2), BB * THN, FS, AS);
    mm1(mk(ps, SS, Ws_h, Ws_l, bs, nullptr, 0,
           xs_h + (size_t)(TT - 1) * BB * FS, FS, 1, 0), BB, FS, SS);

    // batched: layer-0 prefix input gates; future action embeddings + gates
    mm1(mk(xs_h, FS, Wih0h, Wih0l, bih0, gi, G3, nullptr, 0, 0, 0), TT * BB, G3, FS);
    mm1(mk(fa, AS, Wa_h, Wa_l, ba, nullptr, 0, xa, FS, 1, 3), BB * TFN, FS, AS);
    mm1(mk(xa, FS, Wih0h, Wih0l, bih0, gia, G3, nullptr, 0, 0, 0), TFN * BB, G3, FS);

    // ---- persistent two-layer prefix scan (66 phases, one launch) ----
    scan_kernel<<<144, 256, SMEM_BYTES>>>(
        h0f, h1f, h0h, h1h,
        Whh0h, Whh0l, Wih1h, Wih1l, Whh1h, Whh1l,
        bhh0, bih1, bhh1, gi, gh0b, gi1b, gh1b);

    auto combine = [&](const float* a, const float* b, float* hf, __half* hh) {
        gru_combine1<<<(BB * FS / 2) / 256, 256>>>(a, b, hf, hh);
    };

    // ---- future rollout (split-K on all serial GEMMs) ----
    for (int t = 0; t < TFN; t++) {
        mm1(mk(h0h, FS, Whh0h, Whh0l, bhh0, gh0b, G3, nullptr, 0, 0, 0),
            BB, G3, FS, 3);
        combine(gia + (size_t)t * BB * G3, gh0b, h0f, h0h);
        mm2(mk(h0h, FS, Wih1h, Wih1l, bih1, gi1b, G3, nullptr, 0, 0, 0),
            mk(h1h, FS, Whh1h, Whh1l, bhh1, gh1b, G3, nullptr, 0, 0, 0),
            BB, G3, FS, 3);
        combine(gi1b, gh1b, h1f, h1h);

        reward_kernel<<<(BB * 32 + 255) / 256, 256>>>(h1f, Wr, br, out_r, t);
        mm1(mk(h1h, FS, Ws2_h, Ws2_l, bs2,
               out_s + (size_t)t * SS, (int64_t)TFN * SS, sh, SS, 1, 0),
            BB, SS, FS, 6);
        mm1(mk(sh, SS, Ws_h, Ws_l, bs, nullptr, 0, xh, FS, 1, 0),
            BB, FS, SS, 3);

        mm2(mk(xh,  FS, Wih0h, Wih0l, bih0, gi1b, G3, nullptr, 0, 0, 0),
            mk(h0h, FS, Whh0h, Whh0l, bhh0, gh0b, G3, nullptr, 0, 0, 0),
            BB, G3, FS, 3);
        combine(gi1b, gh0b, h0f, h0h);
        mm2(mk(h0h, FS, Wih1h, Wih1l, bih1, gi1b, G3, nullptr, 0, 0, 0),
            mk(h1h, FS, Whh1h, Whh1l, bhh1, gh1b, G3, nullptr, 0, 0, 0),
            BB, G3, FS, 3);
        combine(gi1b, gh1b, h1f, h1h);
    }
}